// round 4
// baseline (speedup 1.0000x reference)
#include <cuda_runtime.h>
#include <cuda_fp16.h>

// ---------------------------------------------------------------------------
// GraphSAGE: out = mean_agg(x) @ W + x @ RW + bias    (N=100k, E=1.28M, D=64)
//   convert : x (fp32) -> g_xh (fp16)                [independent]
//   zero    : deg, cur = 0
//   count   : deg[row]++
//   scan    : exclusive prefix sum (block partials -> warp scan -> offsets)
//   fill    : CSR adjacency
//   fused   : 64-node tile: fp16 gather-mean -> smem(transposed),
//             then [64 x 128]@[128 x 64] GEMM with fma.rn.f32x2,
//             weights pre-duplicated in smem (no mov-dup in inner loop)
// ---------------------------------------------------------------------------

#define NMAX 100000
#define EMAX 1280000
#define D 64
#define TN 64
#define SCAN_CHUNK 512

typedef unsigned long long ull;

__device__ int  g_deg[NMAX];
__device__ int  g_offs[NMAX];
__device__ int  g_cur[NMAX];
__device__ int  g_csr[EMAX];
__device__ int  g_part[256];
__device__ int  g_partoff[256];
__device__ __half g_xh[(size_t)NMAX * D];   // 12.8 MB fp16 copy of x

// ---------------- convert x -> fp16 ----------------
__global__ void convert_kernel(const float4* __restrict__ x4, int n4) {
    int i = blockIdx.x * blockDim.x + threadIdx.x;
    int stride = gridDim.x * blockDim.x;
    ull* dst = reinterpret_cast<ull*>(g_xh);
    for (int k = i; k < n4; k += stride) {
        float4 v = x4[k];
        __half2 lo = __floats2half2_rn(v.x, v.y);
        __half2 hi = __floats2half2_rn(v.z, v.w);
        unsigned ulo = *reinterpret_cast<unsigned*>(&lo);
        unsigned uhi = *reinterpret_cast<unsigned*>(&hi);
        dst[k] = ((ull)uhi << 32) | (ull)ulo;
    }
}

// ---------------- zero ----------------
__global__ void zero_kernel(int N) {
    int i = blockIdx.x * blockDim.x + threadIdx.x;
    int stride = gridDim.x * blockDim.x;
    for (int k = i; k < N; k += stride) { g_deg[k] = 0; g_cur[k] = 0; }
}

// ---------------- degree count ----------------
__global__ void count_kernel(const int* __restrict__ ei, int E) {
    int e = blockIdx.x * blockDim.x + threadIdx.x;
    if (e < E) atomicAdd(&g_deg[ei[e]], 1);
}

// ---------------- scan a: per-block partials ----------------
__global__ void scan_a(int N) {
    __shared__ int sm[256];
    int b = blockIdx.x, t = threadIdx.x;
    int i0 = b * SCAN_CHUNK + t * 2;
    int v = 0;
    if (i0 < N)     v += g_deg[i0];
    if (i0 + 1 < N) v += g_deg[i0 + 1];
    sm[t] = v; __syncthreads();
    #pragma unroll
    for (int s = 128; s > 0; s >>= 1) {
        if (t < s) sm[t] += sm[t + s];
        __syncthreads();
    }
    if (t == 0) g_part[b] = sm[0];
}

// ---------------- scan b: single warp over <=256 partials ----------------
__global__ void scan_b(int nb) {
    int lane = threadIdx.x;
    int v[8]; int tot = 0;
    #pragma unroll
    for (int i = 0; i < 8; i++) {
        int idx = lane * 8 + i;
        int t = (idx < nb) ? g_part[idx] : 0;
        v[i] = tot; tot += t;
    }
    int s = tot;
    #pragma unroll
    for (int dlt = 1; dlt < 32; dlt <<= 1) {
        int u = __shfl_up_sync(0xffffffffu, s, dlt);
        if (lane >= dlt) s += u;
    }
    int ex = s - tot;   // exclusive prefix of lane totals
    #pragma unroll
    for (int i = 0; i < 8; i++) {
        int idx = lane * 8 + i;
        if (idx < nb) g_partoff[idx] = ex + v[i];
    }
}

// ---------------- scan c: exclusive offsets ----------------
__global__ void scan_c(int N) {
    __shared__ int sm[256];
    int b = blockIdx.x, t = threadIdx.x;
    int i0 = b * SCAN_CHUNK + t * 2;
    int d0 = (i0 < N) ? g_deg[i0] : 0;
    int d1 = (i0 + 1 < N) ? g_deg[i0 + 1] : 0;
    int own = d0 + d1;
    sm[t] = own; __syncthreads();
    #pragma unroll
    for (int s = 1; s < 256; s <<= 1) {
        int u = (t >= s) ? sm[t - s] : 0;
        __syncthreads();
        sm[t] += u;
        __syncthreads();
    }
    int base = g_partoff[b] + sm[t] - own;
    if (i0 < N)     g_offs[i0] = base;
    if (i0 + 1 < N) g_offs[i0 + 1] = base + d0;
}

// ---------------- CSR fill ----------------
__global__ void fill_kernel(const int* __restrict__ ei, int E) {
    int e = blockIdx.x * blockDim.x + threadIdx.x;
    if (e >= E) return;
    int r = ei[e];
    int c = ei[E + e];
    int p = atomicAdd(&g_cur[r], 1);
    g_csr[g_offs[r] + p] = c;
}

// ---------------- fused gather-mean + GEMM ----------------
// dynamic smem:
//   float Apf[128][66]   33792 B   A transposed: Apf[k][node_local]
//   ull   Wd [128][64]   65536 B   Wd[k][j] = (w,w) duplicated pair
#define APF_PAD 66
#define APF_BYTES (128 * APF_PAD * 4)
#define SMEM_BYTES (APF_BYTES + 128 * 64 * 8)

__global__ void __launch_bounds__(256) fused_kernel(
    const float2* __restrict__ x2,
    const float* __restrict__ Wm,
    const float* __restrict__ RWm,
    const float* __restrict__ bias,
    float* __restrict__ out, int N)
{
    extern __shared__ char smem[];
    float* Apf = reinterpret_cast<float*>(smem);
    ull*   Wd  = reinterpret_cast<ull*>(smem + APF_BYTES);

    int tid = threadIdx.x, lane = tid & 31, w = tid >> 5;

    // stage duplicated weights: Wd[k][j] = (Wc[k][j], Wc[k][j])
    for (int i = tid; i < 128 * 64; i += 256) {
        int k = i >> 6, j = i & 63;
        float wv = (k < 64) ? Wm[k * 64 + j] : RWm[(k - 64) * 64 + j];
        reinterpret_cast<float2*>(Wd)[i] = make_float2(wv, wv);
    }

    int nodeBase = blockIdx.x * TN;
    const ull* xh8 = reinterpret_cast<const ull*>(g_xh);   // 16 ull per row
    int half16 = lane & 15;
    bool loHalf = (lane < 16);

    // ---- phase 1: gather (warp w -> 8 nodes) ----
    for (int s = 0; s < 8; s++) {
        int nloc = w * 8 + s;
        int g = nodeBase + nloc;
        float a0 = 0.f, a1 = 0.f, a2 = 0.f, a3 = 0.f;
        int d = 0;
        if (g < N) {
            d = g_deg[g];
            int off = g_offs[g];
            for (int base = 0; base < d; base += 32) {
                int m = d - base; if (m > 32) m = 32;
                int colv = (lane < m) ? g_csr[off + base + lane] : -1;
                int j = 0;
                for (; j + 4 <= m; j += 4) {
                    int cA0 = __shfl_sync(0xffffffffu, colv, j);
                    int cB0 = __shfl_sync(0xffffffffu, colv, j + 1);
                    int cA1 = __shfl_sync(0xffffffffu, colv, j + 2);
                    int cB1 = __shfl_sync(0xffffffffu, colv, j + 3);
                    int c0 = loHalf ? cA0 : cB0;
                    int c1 = loHalf ? cA1 : cB1;
                    ull v0 = __ldg(&xh8[(long)c0 * 16 + half16]);
                    ull v1 = __ldg(&xh8[(long)c1 * 16 + half16]);
                    {
                        unsigned lo = (unsigned)v0, hi = (unsigned)(v0 >> 32);
                        float2 f01 = __half22float2(*reinterpret_cast<__half2*>(&lo));
                        float2 f23 = __half22float2(*reinterpret_cast<__half2*>(&hi));
                        a0 += f01.x; a1 += f01.y; a2 += f23.x; a3 += f23.y;
                    }
                    {
                        unsigned lo = (unsigned)v1, hi = (unsigned)(v1 >> 32);
                        float2 f01 = __half22float2(*reinterpret_cast<__half2*>(&lo));
                        float2 f23 = __half22float2(*reinterpret_cast<__half2*>(&hi));
                        a0 += f01.x; a1 += f01.y; a2 += f23.x; a3 += f23.y;
                    }
                }
                for (; j < m; j += 2) {
                    int cA = __shfl_sync(0xffffffffu, colv, j);
                    int cB = (j + 1 < 32) ? __shfl_sync(0xffffffffu, colv, j + 1) : -1;
                    if (j + 1 >= m) cB = -1;
                    int c = loHalf ? cA : cB;
                    if (c >= 0) {
                        ull v0 = __ldg(&xh8[(long)c * 16 + half16]);
                        unsigned lo = (unsigned)v0, hi = (unsigned)(v0 >> 32);
                        float2 f01 = __half22float2(*reinterpret_cast<__half2*>(&lo));
                        float2 f23 = __half22float2(*reinterpret_cast<__half2*>(&hi));
                        a0 += f01.x; a1 += f01.y; a2 += f23.x; a3 += f23.y;
                    }
                }
            }
        }
        // combine the two half-warps (each accumulated alternating edges)
        a0 += __shfl_xor_sync(0xffffffffu, a0, 16);
        a1 += __shfl_xor_sync(0xffffffffu, a1, 16);
        a2 += __shfl_xor_sync(0xffffffffu, a2, 16);
        a3 += __shfl_xor_sync(0xffffffffu, a3, 16);

        float inv = 1.0f / (float)(d > 0 ? d : 1);
        if (loHalf) {
            int k0 = 4 * half16;
            Apf[(k0 + 0) * APF_PAD + nloc] = a0 * inv;
            Apf[(k0 + 1) * APF_PAD + nloc] = a1 * inv;
            Apf[(k0 + 2) * APF_PAD + nloc] = a2 * inv;
            Apf[(k0 + 3) * APF_PAD + nloc] = a3 * inv;
        }
        // self term (fp32, exact)
        float2 xv = (g < N) ? x2[(long)g * 32 + lane] : make_float2(0.f, 0.f);
        Apf[(64 + 2 * lane) * APF_PAD + nloc] = xv.x;
        Apf[(64 + 2 * lane + 1) * APF_PAD + nloc] = xv.y;
    }
    __syncthreads();

    // ---- phase 2: GEMM. warp w -> nodes 8w..8w+7 (4 packed pairs); lane j ->
    //      output cols j and j+32. acc[p][0] = (out[2p][j], out[2p+1][j]) etc.
    int j = lane;
    float bb0 = bias[j], bb1 = bias[j + 32];
    ull accA0, accA1, accB0, accB1, accC0, accC1, accD0, accD1;
    asm("mov.b64 %0, {%1, %1};" : "=l"(accA0) : "f"(bb0));
    asm("mov.b64 %0, {%1, %1};" : "=l"(accA1) : "f"(bb1));
    accB0 = accA0; accC0 = accA0; accD0 = accA0;
    accB1 = accA1; accC1 = accA1; accD1 = accA1;

    int an = 8 * w;   // local node base for this warp (even)

    #pragma unroll 4
    for (int k = 0; k < 128; k++) {
        const ull* arow = reinterpret_cast<const ull*>(&Apf[k * APF_PAD + an]);
        ull aA = arow[0];
        ull aB = arow[1];
        ull aC = arow[2];
        ull aD = arow[3];
        ull w0 = Wd[k * 64 + j];
        ull w1 = Wd[k * 64 + j + 32];
        asm("fma.rn.f32x2 %0, %1, %2, %0;" : "+l"(accA0) : "l"(aA), "l"(w0));
        asm("fma.rn.f32x2 %0, %1, %2, %0;" : "+l"(accA1) : "l"(aA), "l"(w1));
        asm("fma.rn.f32x2 %0, %1, %2, %0;" : "+l"(accB0) : "l"(aB), "l"(w0));
        asm("fma.rn.f32x2 %0, %1, %2, %0;" : "+l"(accB1) : "l"(aB), "l"(w1));
        asm("fma.rn.f32x2 %0, %1, %2, %0;" : "+l"(accC0) : "l"(aC), "l"(w0));
        asm("fma.rn.f32x2 %0, %1, %2, %0;" : "+l"(accC1) : "l"(aC), "l"(w1));
        asm("fma.rn.f32x2 %0, %1, %2, %0;" : "+l"(accD0) : "l"(aD), "l"(w0));
        asm("fma.rn.f32x2 %0, %1, %2, %0;" : "+l"(accD1) : "l"(aD), "l"(w1));
    }

    // ---- write out: acc lo -> even node, hi -> odd node ----
    ull accs[8] = {accA0, accA1, accB0, accB1, accC0, accC1, accD0, accD1};
    #pragma unroll
    for (int p = 0; p < 4; p++) {
        int n0 = nodeBase + an + 2 * p;
        float lo0, hi0, lo1, hi1;
        asm("mov.b64 {%0, %1}, %2;" : "=f"(lo0), "=f"(hi0) : "l"(accs[2 * p]));
        asm("mov.b64 {%0, %1}, %2;" : "=f"(lo1), "=f"(hi1) : "l"(accs[2 * p + 1]));
        if (n0 < N) {
            out[(long)n0 * D + j] = lo0;
            out[(long)n0 * D + j + 32] = lo1;
        }
        if (n0 + 1 < N) {
            out[(long)(n0 + 1) * D + j] = hi0;
            out[(long)(n0 + 1) * D + j + 32] = hi1;
        }
    }
}

// ---------------- launch ----------------
extern "C" void kernel_launch(void* const* d_in, const int* in_sizes, int n_in,
                              void* d_out, int out_size) {
    const float* x    = (const float*)d_in[0];
    const int*   ei   = (const int*)d_in[1];
    const float* W    = (const float*)d_in[2];
    const float* RW   = (const float*)d_in[3];
    const float* bias = (const float*)d_in[4];
    float* out = (float*)d_out;

    int N = in_sizes[0] / D;
    int E = in_sizes[1] / 2;
    if (N > NMAX) N = NMAX;
    if (E > EMAX) E = EMAX;

    int nb = (N + SCAN_CHUNK - 1) / SCAN_CHUNK;

    static bool attr_set = false;
    if (!attr_set) {
        cudaFuncSetAttribute(fused_kernel,
                             cudaFuncAttributeMaxDynamicSharedMemorySize,
                             SMEM_BYTES);
        attr_set = true;
    }

    convert_kernel<<<1024, 256>>>(reinterpret_cast<const float4*>(x), N * (D / 4));
    zero_kernel<<<400, 256>>>(N);
    count_kernel<<<(E + 255) / 256, 256>>>(ei, E);
    scan_a<<<nb, 256>>>(N);
    scan_b<<<1, 32>>>(nb);
    scan_c<<<nb, 256>>>(N);
    fill_kernel<<<(E + 255) / 256, 256>>>(ei, E);
    fused_kernel<<<(N + TN - 1) / TN, 256, SMEM_BYTES>>>(
        reinterpret_cast<const float2*>(x), W, RW, bias, out, N);
}

// round 5
// speedup vs baseline: 2.3100x; 2.3100x over previous
#include <cuda_runtime.h>
#include <cuda_fp16.h>

// ---------------------------------------------------------------------------
// GraphSAGE: out = mean_agg(x) @ W + x @ RW + bias    (N=100k, E=1.28M, D=64)
//   prep  : zero deg/cur/total, x->fp16 (g_xh), build WT fp16 (g_wt)
//   count : deg[row]++
//   alloc : exclusive offsets via block scan + one global atomicAdd per block
//   fill  : CSR adjacency
//   fused : 64-node tile: fp16 gather-mean -> smem A[64][128],
//           tensor-core GEMM  C[64][64] = A[64][128] @ WT^T  (mma.m16n8k16)
// ---------------------------------------------------------------------------

#define NMAX 100000
#define EMAX 1280000
#define D 64
#define TN 64

typedef unsigned long long ull;

__device__ int      g_deg[NMAX];
__device__ int      g_offs[NMAX];
__device__ int      g_cur[NMAX];
__device__ int      g_csr[EMAX];
__device__ int      g_total;
__device__ __half   g_xh[(size_t)NMAX * D];     // fp16 copy of x (12.8 MB)
__device__ unsigned g_wt[64 * 64];              // WT half2: [col j][k-pair kk]

// ---------------- prep: zeros + conversions ----------------
__global__ void prep_kernel(const float4* __restrict__ x4, int n4,
                            const float* __restrict__ Wm,
                            const float* __restrict__ RWm, int N) {
    int gid = blockIdx.x * blockDim.x + threadIdx.x;
    int stride = gridDim.x * blockDim.x;

    if (gid == 0) g_total = 0;
    for (int k = gid; k < N; k += stride) { g_deg[k] = 0; g_cur[k] = 0; }

    // x -> fp16 (packed 4 floats -> 4 halves per iter)
    ull* dst = reinterpret_cast<ull*>(g_xh);
    for (int k = gid; k < n4; k += stride) {
        float4 v = x4[k];
        __half2 lo = __floats2half2_rn(v.x, v.y);
        __half2 hi = __floats2half2_rn(v.z, v.w);
        unsigned ulo = *reinterpret_cast<unsigned*>(&lo);
        unsigned uhi = *reinterpret_cast<unsigned*>(&hi);
        dst[k] = ((ull)uhi << 32) | (ull)ulo;
    }

    // WT[j][kk] = half2( Wc[2kk][j], Wc[2kk+1][j] ),  Wc = concat(W; RW) rows
    if (gid < 64 * 64) {
        int j = gid >> 6, kk = gid & 63;
        int k0 = 2 * kk;
        float w0 = (k0 < 64) ? Wm[k0 * 64 + j] : RWm[(k0 - 64) * 64 + j];
        float w1 = (k0 + 1 < 64) ? Wm[(k0 + 1) * 64 + j] : RWm[(k0 + 1 - 64) * 64 + j];
        __half2 h = __floats2half2_rn(w0, w1);
        g_wt[gid] = *reinterpret_cast<unsigned*>(&h);
    }
}

// ---------------- count ----------------
__global__ void count_kernel(const int* __restrict__ ei, int E) {
    int e = blockIdx.x * blockDim.x + threadIdx.x;
    if (e < E) atomicAdd(&g_deg[ei[e]], 1);
}

// ---------------- alloc: block-scan + global atomic base ----------------
__global__ void alloc_kernel(int N) {
    int t = threadIdx.x;
    int i = blockIdx.x * 256 + t;
    int d = (i < N) ? g_deg[i] : 0;
    int lane = t & 31, wrp = t >> 5;

    int v = d;
    #pragma unroll
    for (int s = 1; s < 32; s <<= 1) {
        int u = __shfl_up_sync(0xffffffffu, v, s);
        if (lane >= s) v += u;
    }
    __shared__ int wsum[8];
    __shared__ int gbase;
    if (lane == 31) wsum[wrp] = v;
    __syncthreads();
    if (t == 0) {
        int acc = 0;
        #pragma unroll
        for (int k = 0; k < 8; k++) { int tmp = wsum[k]; wsum[k] = acc; acc += tmp; }
        gbase = atomicAdd(&g_total, acc);
    }
    __syncthreads();
    if (i < N) g_offs[i] = gbase + wsum[wrp] + v - d;
}

// ---------------- fill ----------------
__global__ void fill_kernel(const int* __restrict__ ei, int E) {
    int e = blockIdx.x * blockDim.x + threadIdx.x;
    if (e >= E) return;
    int r = ei[e];
    int c = ei[E + e];
    int p = atomicAdd(&g_cur[r], 1);
    g_csr[g_offs[r] + p] = c;
}

// ---------------- fused gather-mean + tensor-core GEMM ----------------
// smem (words = half2):
//   Ah[64 rows][68 words]  (row = node, halves k 0..127; 4-word row pad)
//   Wt[64 cols][68 words]  (col-major W^T, same pad)
// pad 68: row stride mod 32 = 4 words -> fragment reads conflict-free.
#define ROWW 68

__global__ void __launch_bounds__(256) fused_kernel(
    const float* __restrict__ bias,
    float* __restrict__ out, int N)
{
    __shared__ unsigned Ah[64 * ROWW];
    __shared__ unsigned Wt[64 * ROWW];

    int tid = threadIdx.x, lane = tid & 31, w = tid >> 5;

    // stage WT (16 KB, repack with pad)
    for (int i = tid; i < 64 * 64; i += 256) {
        int j = i >> 6, kk = i & 63;
        Wt[j * ROWW + kk] = g_wt[i];
    }

    int nodeBase = blockIdx.x * TN;
    const unsigned* xw = reinterpret_cast<const unsigned*>(g_xh);  // 32 words/row

    // ---- phase 1: gather. warp w -> nodes w*8 .. w*8+7 ----
    for (int s = 0; s < 8; s++) {
        int nloc = w * 8 + s;
        int g = nodeBase + nloc;
        int d = 0, off = 0;
        if (g < N) { d = g_deg[g]; off = g_offs[g]; }
        float ax = 0.f, ay = 0.f;

        for (int base = 0; base < d; base += 32) {
            int m = d - base; if (m > 32) m = 32;
            int colv = (lane < m) ? g_csr[off + base + lane] : 0;
            int j = 0;
            for (; j + 4 <= m; j += 4) {
                int c0 = __shfl_sync(0xffffffffu, colv, j);
                int c1 = __shfl_sync(0xffffffffu, colv, j + 1);
                int c2 = __shfl_sync(0xffffffffu, colv, j + 2);
                int c3 = __shfl_sync(0xffffffffu, colv, j + 3);
                unsigned u0 = __ldg(&xw[c0 * 32 + lane]);
                unsigned u1 = __ldg(&xw[c1 * 32 + lane]);
                unsigned u2 = __ldg(&xw[c2 * 32 + lane]);
                unsigned u3 = __ldg(&xw[c3 * 32 + lane]);
                float2 f0 = __half22float2(*reinterpret_cast<__half2*>(&u0));
                float2 f1 = __half22float2(*reinterpret_cast<__half2*>(&u1));
                float2 f2 = __half22float2(*reinterpret_cast<__half2*>(&u2));
                float2 f3 = __half22float2(*reinterpret_cast<__half2*>(&u3));
                ax += (f0.x + f1.x) + (f2.x + f3.x);
                ay += (f0.y + f1.y) + (f2.y + f3.y);
            }
            for (; j < m; j++) {
                int c = __shfl_sync(0xffffffffu, colv, j);
                unsigned u = __ldg(&xw[c * 32 + lane]);
                float2 f = __half22float2(*reinterpret_cast<__half2*>(&u));
                ax += f.x; ay += f.y;
            }
        }
        float inv = 1.0f / (float)(d > 0 ? d : 1);
        __half2 h = __floats2half2_rn(ax * inv, ay * inv);
        Ah[nloc * ROWW + lane] = *reinterpret_cast<unsigned*>(&h);
        // self term (k 64..127) straight from fp16 x
        unsigned sv = (g < N) ? __ldg(&xw[(long)g * 32 + lane]) : 0u;
        Ah[nloc * ROWW + 32 + lane] = sv;
    }
    __syncthreads();

    // ---- phase 2: tensor-core GEMM ----
    // warp w: mtile = w&3 (16 rows), nhalf = w>>2 (32 cols = 4 n-tiles of 8)
    int gq = lane >> 2, t4 = lane & 3;
    int mtile = w & 3, nhalf = w >> 2;
    int rowA0 = (mtile * 16 + gq) * ROWW;
    int rowA1 = rowA0 + 8 * ROWW;

    float acc[4][4];
    #pragma unroll
    for (int nt = 0; nt < 4; nt++) {
        int colbase = nhalf * 32 + nt * 8;
        float blo = __ldg(&bias[colbase + 2 * t4]);
        float bhi = __ldg(&bias[colbase + 2 * t4 + 1]);
        acc[nt][0] = blo; acc[nt][1] = bhi;
        acc[nt][2] = blo; acc[nt][3] = bhi;
    }

    #pragma unroll
    for (int k0w = 0; k0w < 64; k0w += 8) {   // 16 halves per step
        unsigned a0 = Ah[rowA0 + k0w + t4];
        unsigned a1 = Ah[rowA1 + k0w + t4];
        unsigned a2 = Ah[rowA0 + k0w + 4 + t4];
        unsigned a3 = Ah[rowA1 + k0w + 4 + t4];
        #pragma unroll
        for (int nt = 0; nt < 4; nt++) {
            int colw = (nhalf * 32 + nt * 8 + gq) * ROWW + k0w;
            unsigned b0 = Wt[colw + t4];
            unsigned b1 = Wt[colw + 4 + t4];
            asm volatile(
                "mma.sync.aligned.m16n8k16.row.col.f32.f16.f16.f32 "
                "{%0,%1,%2,%3}, {%4,%5,%6,%7}, {%8,%9}, {%0,%1,%2,%3};\n"
                : "+f"(acc[nt][0]), "+f"(acc[nt][1]),
                  "+f"(acc[nt][2]), "+f"(acc[nt][3])
                : "r"(a0), "r"(a1), "r"(a2), "r"(a3), "r"(b0), "r"(b1));
        }
    }

    // ---- store ----
    int n0 = nodeBase + mtile * 16 + gq;
    int n1 = n0 + 8;
    #pragma unroll
    for (int nt = 0; nt < 4; nt++) {
        int col = nhalf * 32 + nt * 8 + 2 * t4;
        if (n0 < N)
            *reinterpret_cast<float2*>(&out[(long)n0 * D + col]) =
                make_float2(acc[nt][0], acc[nt][1]);
        if (n1 < N)
            *reinterpret_cast<float2*>(&out[(long)n1 * D + col]) =
                make_float2(acc[nt][2], acc[nt][3]);
    }
}

// ---------------- launch ----------------
extern "C" void kernel_launch(void* const* d_in, const int* in_sizes, int n_in,
                              void* d_out, int out_size) {
    const float* x    = (const float*)d_in[0];
    const int*   ei   = (const int*)d_in[1];
    const float* W    = (const float*)d_in[2];
    const float* RW   = (const float*)d_in[3];
    const float* bias = (const float*)d_in[4];
    float* out = (float*)d_out;

    int N = in_sizes[0] / D;
    int E = in_sizes[1] / 2;
    if (N > NMAX) N = NMAX;
    if (E > EMAX) E = EMAX;

    prep_kernel<<<1024, 256>>>(reinterpret_cast<const float4*>(x),
                               N * (D / 4), W, RW, N);
    count_kernel<<<(E + 255) / 256, 256>>>(ei, E);
    alloc_kernel<<<(N + 255) / 256, 256>>>(N);
    fill_kernel<<<(E + 255) / 256, 256>>>(ei, E);
    fused_kernel<<<(N + TN - 1) / TN, 256>>>(bias, out, N);
}

// round 6
// speedup vs baseline: 2.3399x; 1.0129x over previous
#include <cuda_runtime.h>
#include <cuda_fp16.h>

// ---------------------------------------------------------------------------
// GraphSAGE: out = mean_agg(x) @ W + x @ RW + bias    (N=100k, E=1.28M, D=64)
//   prep  : zero deg/total, x->fp16 (g_xh), build WT fp16 (g_wt)
//   count : deg[row]++           (4 edges/thread, int4 loads, REDG)
//   alloc : exclusive offsets via block scan + global atomic base;
//           writes BOTH g_offs (for fused) and g_cur=offs (fill cursor)
//   fill  : p = atomicAdd(&g_cur[r]); csr[p] = c   (2 edges/thread, int2)
//   fused : 64-node tile: fp16 gather-mean (8-deep MLP) -> smem A[64][128],
//           tensor-core GEMM  C[64][64] = A @ WT^T  (mma.m16n8k16)
// ---------------------------------------------------------------------------

#define NMAX 100000
#define EMAX 1280000
#define D 64
#define TN 64

typedef unsigned long long ull;

__device__ int      g_deg[NMAX];
__device__ int      g_offs[NMAX];
__device__ int      g_cur[NMAX];
__device__ int      g_csr[EMAX];
__device__ int      g_total;
__device__ __half   g_xh[(size_t)NMAX * D];     // fp16 copy of x (12.8 MB)
__device__ unsigned g_wt[64 * 64];              // WT half2: [col j][k-pair kk]

// ---------------- prep: zeros + conversions ----------------
__global__ void prep_kernel(const float4* __restrict__ x4, int n4,
                            const float* __restrict__ Wm,
                            const float* __restrict__ RWm, int N) {
    int gid = blockIdx.x * blockDim.x + threadIdx.x;
    int stride = gridDim.x * blockDim.x;

    if (gid == 0) g_total = 0;
    for (int k = gid; k < N; k += stride) g_deg[k] = 0;

    // x -> fp16 (packed 4 floats -> 4 halves per iter)
    ull* dst = reinterpret_cast<ull*>(g_xh);
    for (int k = gid; k < n4; k += stride) {
        float4 v = x4[k];
        __half2 lo = __floats2half2_rn(v.x, v.y);
        __half2 hi = __floats2half2_rn(v.z, v.w);
        unsigned ulo = *reinterpret_cast<unsigned*>(&lo);
        unsigned uhi = *reinterpret_cast<unsigned*>(&hi);
        dst[k] = ((ull)uhi << 32) | (ull)ulo;
    }

    // WT[j][kk] = half2( Wc[2kk][j], Wc[2kk+1][j] ),  Wc = concat(W; RW) rows
    if (gid < 64 * 64) {
        int j = gid >> 6, kk = gid & 63;
        int k0 = 2 * kk;
        float w0 = (k0 < 64) ? Wm[k0 * 64 + j] : RWm[(k0 - 64) * 64 + j];
        float w1 = (k0 + 1 < 64) ? Wm[(k0 + 1) * 64 + j] : RWm[(k0 + 1 - 64) * 64 + j];
        __half2 h = __floats2half2_rn(w0, w1);
        g_wt[gid] = *reinterpret_cast<unsigned*>(&h);
    }
}

// ---------------- count: 4 edges/thread ----------------
__global__ void count_kernel(const int* __restrict__ ei, int E) {
    int t = blockIdx.x * blockDim.x + threadIdx.x;
    int e4 = t * 4;
    if (e4 + 4 <= E) {
        int4 r = *reinterpret_cast<const int4*>(ei + e4);
        atomicAdd(&g_deg[r.x], 1);
        atomicAdd(&g_deg[r.y], 1);
        atomicAdd(&g_deg[r.z], 1);
        atomicAdd(&g_deg[r.w], 1);
    } else {
        for (int e = e4; e < E; e++) atomicAdd(&g_deg[ei[e]], 1);
    }
}

// ---------------- alloc: block-scan + global atomic base ----------------
__global__ void alloc_kernel(int N) {
    int t = threadIdx.x;
    int i = blockIdx.x * 256 + t;
    int d = (i < N) ? g_deg[i] : 0;
    int lane = t & 31, wrp = t >> 5;

    int v = d;
    #pragma unroll
    for (int s = 1; s < 32; s <<= 1) {
        int u = __shfl_up_sync(0xffffffffu, v, s);
        if (lane >= s) v += u;
    }
    __shared__ int wsum[8];
    __shared__ int gbase;
    if (lane == 31) wsum[wrp] = v;
    __syncthreads();
    if (t == 0) {
        int acc = 0;
        #pragma unroll
        for (int k = 0; k < 8; k++) { int tmp = wsum[k]; wsum[k] = acc; acc += tmp; }
        gbase = atomicAdd(&g_total, acc);
    }
    __syncthreads();
    if (i < N) {
        int off = gbase + wsum[wrp] + v - d;
        g_offs[i] = off;
        g_cur[i]  = off;   // fill cursor pre-seeded with the offset
    }
}

// ---------------- fill: 2 edges/thread, cursor carries offset ----------------
__global__ void fill_kernel(const int* __restrict__ ei, int E) {
    int t = blockIdx.x * blockDim.x + threadIdx.x;
    int e2 = t * 2;
    if (e2 + 2 <= E) {
        int2 r = *reinterpret_cast<const int2*>(ei + e2);
        int2 c = *reinterpret_cast<const int2*>(ei + E + e2);
        int p0 = atomicAdd(&g_cur[r.x], 1);
        int p1 = atomicAdd(&g_cur[r.y], 1);
        g_csr[p0] = c.x;
        g_csr[p1] = c.y;
    } else if (e2 < E) {
        int r = ei[e2], c = ei[E + e2];
        int p = atomicAdd(&g_cur[r], 1);
        g_csr[p] = c;
    }
}

// ---------------- fused gather-mean + tensor-core GEMM ----------------
// smem (words = half2):
//   Ah[64 rows][68 words]  (row = node, halves k 0..127; 4-word row pad)
//   Wt[64 cols][68 words]  (col-major W^T, same pad)
#define ROWW 68

__global__ void __launch_bounds__(256) fused_kernel(
    const float* __restrict__ bias,
    float* __restrict__ out, int N)
{
    __shared__ unsigned Ah[64 * ROWW];
    __shared__ unsigned Wt[64 * ROWW];

    int tid = threadIdx.x, lane = tid & 31, w = tid >> 5;

    // stage WT (16 KB, repack with pad)
    for (int i = tid; i < 64 * 64; i += 256) {
        int j = i >> 6, kk = i & 63;
        Wt[j * ROWW + kk] = g_wt[i];
    }

    int nodeBase = blockIdx.x * TN;
    const unsigned* xw = reinterpret_cast<const unsigned*>(g_xh);  // 32 words/row

    // ---- phase 1: gather. warp w -> nodes w*8 .. w*8+7; MLP=8 ----
    for (int s = 0; s < 8; s++) {
        int nloc = w * 8 + s;
        int g = nodeBase + nloc;
        int d = 0, off = 0;
        if (g < N) { d = g_deg[g]; off = g_offs[g]; }
        float ax = 0.f, ay = 0.f;

        for (int base = 0; base < d; base += 32) {
            int m = d - base; if (m > 32) m = 32;
            int colv = (lane < m) ? g_csr[off + base + lane] : 0;
            int j = 0;
            for (; j + 8 <= m; j += 8) {
                int c0 = __shfl_sync(0xffffffffu, colv, j);
                int c1 = __shfl_sync(0xffffffffu, colv, j + 1);
                int c2 = __shfl_sync(0xffffffffu, colv, j + 2);
                int c3 = __shfl_sync(0xffffffffu, colv, j + 3);
                int c4 = __shfl_sync(0xffffffffu, colv, j + 4);
                int c5 = __shfl_sync(0xffffffffu, colv, j + 5);
                int c6 = __shfl_sync(0xffffffffu, colv, j + 6);
                int c7 = __shfl_sync(0xffffffffu, colv, j + 7);
                unsigned u0 = __ldg(&xw[c0 * 32 + lane]);
                unsigned u1 = __ldg(&xw[c1 * 32 + lane]);
                unsigned u2 = __ldg(&xw[c2 * 32 + lane]);
                unsigned u3 = __ldg(&xw[c3 * 32 + lane]);
                unsigned u4 = __ldg(&xw[c4 * 32 + lane]);
                unsigned u5 = __ldg(&xw[c5 * 32 + lane]);
                unsigned u6 = __ldg(&xw[c6 * 32 + lane]);
                unsigned u7 = __ldg(&xw[c7 * 32 + lane]);
                float2 f0 = __half22float2(*reinterpret_cast<__half2*>(&u0));
                float2 f1 = __half22float2(*reinterpret_cast<__half2*>(&u1));
                float2 f2 = __half22float2(*reinterpret_cast<__half2*>(&u2));
                float2 f3 = __half22float2(*reinterpret_cast<__half2*>(&u3));
                float2 f4 = __half22float2(*reinterpret_cast<__half2*>(&u4));
                float2 f5 = __half22float2(*reinterpret_cast<__half2*>(&u5));
                float2 f6 = __half22float2(*reinterpret_cast<__half2*>(&u6));
                float2 f7 = __half22float2(*reinterpret_cast<__half2*>(&u7));
                ax += ((f0.x + f1.x) + (f2.x + f3.x)) + ((f4.x + f5.x) + (f6.x + f7.x));
                ay += ((f0.y + f1.y) + (f2.y + f3.y)) + ((f4.y + f5.y) + (f6.y + f7.y));
            }
            for (; j < m; j++) {
                int c = __shfl_sync(0xffffffffu, colv, j);
                unsigned u = __ldg(&xw[c * 32 + lane]);
                float2 f = __half22float2(*reinterpret_cast<__half2*>(&u));
                ax += f.x; ay += f.y;
            }
        }
        float inv = 1.0f / (float)(d > 0 ? d : 1);
        __half2 h = __floats2half2_rn(ax * inv, ay * inv);
        Ah[nloc * ROWW + lane] = *reinterpret_cast<unsigned*>(&h);
        // self term (k 64..127) straight from fp16 x
        unsigned sv = (g < N) ? __ldg(&xw[(long)g * 32 + lane]) : 0u;
        Ah[nloc * ROWW + 32 + lane] = sv;
    }
    __syncthreads();

    // ---- phase 2: tensor-core GEMM ----
    int gq = lane >> 2, t4 = lane & 3;
    int mtile = w & 3, nhalf = w >> 2;
    int rowA0 = (mtile * 16 + gq) * ROWW;
    int rowA1 = rowA0 + 8 * ROWW;

    float acc[4][4];
    #pragma unroll
    for (int nt = 0; nt < 4; nt++) {
        int colbase = nhalf * 32 + nt * 8;
        float blo = __ldg(&bias[colbase + 2 * t4]);
        float bhi = __ldg(&bias[colbase + 2 * t4 + 1]);
        acc[nt][0] = blo; acc[nt][1] = bhi;
        acc[nt][2] = blo; acc[nt][3] = bhi;
    }

    #pragma unroll
    for (int k0w = 0; k0w < 64; k0w += 8) {   // 16 halves per step
        unsigned a0 = Ah[rowA0 + k0w + t4];
        unsigned a1 = Ah[rowA1 + k0w + t4];
        unsigned a2 = Ah[rowA0 + k0w + 4 + t4];
        unsigned a3 = Ah[rowA1 + k0w + 4 + t4];
        #pragma unroll
        for (int nt = 0; nt < 4; nt++) {
            int colw = (nhalf * 32 + nt * 8 + gq) * ROWW + k0w;
            unsigned b0 = Wt[colw + t4];
            unsigned b1 = Wt[colw + 4 + t4];
            asm volatile(
                "mma.sync.aligned.m16n8k16.row.col.f32.f16.f16.f32 "
                "{%0,%1,%2,%3}, {%4,%5,%6,%7}, {%8,%9}, {%0,%1,%2,%3};\n"
                : "+f"(acc[nt][0]), "+f"(acc[nt][1]),
                  "+f"(acc[nt][2]), "+f"(acc[nt][3])
                : "r"(a0), "r"(a1), "r"(a2), "r"(a3), "r"(b0), "r"(b1));
        }
    }

    // ---- store ----
    int n0 = nodeBase + mtile * 16 + gq;
    int n1 = n0 + 8;
    #pragma unroll
    for (int nt = 0; nt < 4; nt++) {
        int col = nhalf * 32 + nt * 8 + 2 * t4;
        if (n0 < N)
            *reinterpret_cast<float2*>(&out[(long)n0 * D + col]) =
                make_float2(acc[nt][0], acc[nt][1]);
        if (n1 < N)
            *reinterpret_cast<float2*>(&out[(long)n1 * D + col]) =
                make_float2(acc[nt][2], acc[nt][3]);
    }
}

// ---------------- launch ----------------
extern "C" void kernel_launch(void* const* d_in, const int* in_sizes, int n_in,
                              void* d_out, int out_size) {
    const float* x    = (const float*)d_in[0];
    const int*   ei   = (const int*)d_in[1];
    const float* W    = (const float*)d_in[2];
    const float* RW   = (const float*)d_in[3];
    const float* bias = (const float*)d_in[4];
    float* out = (float*)d_out;

    int N = in_sizes[0] / D;
    int E = in_sizes[1] / 2;
    if (N > NMAX) N = NMAX;
    if (E > EMAX) E = EMAX;

    prep_kernel<<<1024, 256>>>(reinterpret_cast<const float4*>(x),
                               N * (D / 4), W, RW, N);
    count_kernel<<<(E / 4 + 255) / 256, 256>>>(ei, E);
    alloc_kernel<<<(N + 255) / 256, 256>>>(N);
    fill_kernel<<<(E / 2 + 255) / 256, 256>>>(ei, E);
    fused_kernel<<<(N + TN - 1) / TN, 256>>>(bias, out, N);
}